// round 15
// baseline (speedup 1.0000x reference)
#include <cuda_runtime.h>
#include <cuda_bf16.h>

#define NB     512
#define GLO    (-6.0f)
#define BW     (12.0f / NB)
#define INVW   (NB / 12.0f)
#define MAXB   4
#define MAXPTS 8192
#define FULLM  0xFFFFFFFFu
#define WIN    512      // rank half-width around block's home ranks
#define TPB    128
#define QPT    2
#define QBLK   (TPB * QPT)   // 256 queries per block
#define SMXP   1024     // max staged pairs (32 KB smem)
#define MAXQ   (2 * MAXB * MAXPTS)

// Point-major sorted points: g_pt[cl][b][i] = {x, y, z, 0.5*||p||^2},
// x-bin sorted; index n holds a +inf pad entry.
__device__ int    g_cnt[2][MAXB][NB];       // histogram counts
__device__ int    g_start[2][MAXB][NB + 1];
__device__ float4 g_pt[2][MAXB][MAXPTS + 1];
__device__ int    g_aux[MAXQ];              // per input point: bin<<16 | rank
__device__ int    g_ovfCnt;
__device__ int4   g_ovf[MAXQ];              // {code, s0, s1, pad}

__device__ __forceinline__ int binOf(float x) {
    int c = (int)floorf((x - GLO) * INVW);
    return min(max(c, 0), NB - 1);
}

// ---- packed f32x2 helpers ----
__device__ __forceinline__ unsigned long long pk2(float lo, float hi) {
    unsigned long long v;
    asm("mov.b64 %0, {%1, %2};" : "=l"(v) : "f"(lo), "f"(hi));
    return v;
}
__device__ __forceinline__ unsigned long long fma2(unsigned long long a,
                                                   unsigned long long b,
                                                   unsigned long long c) {
    unsigned long long d;
    asm("fma.rn.f32x2 %0, %1, %2, %3;" : "=l"(d) : "l"(a), "l"(b), "l"(c));
    return d;
}
__device__ __forceinline__ void unpk2(unsigned long long v, float& lo, float& hi) {
    asm("mov.b64 {%0, %1}, %2;" : "=f"(lo), "=f"(hi) : "l"(v));
}

// ---------------- setup ----------------

__global__ void k_zero(float* out) {
    int i = blockIdx.x * blockDim.x + threadIdx.x;
    int* c = &g_cnt[0][0][0];
    if (i < 2 * MAXB * NB) c[i] = 0;
    if (i == 0) { out[0] = 0.0f; g_ovfCnt = 0; }
}

// Histogram; records each point's (bin, in-bin rank) for atomic-free scatter.
__global__ void k_hist(const float* __restrict__ p1, const float* __restrict__ p2,
                       int B, int N, int M)
{
    int idx = blockIdx.x * blockDim.x + threadIdx.x;
    int tot0 = B * N;
    int cl, b; const float* p;
    if (idx < tot0) {
        cl = 0; b = idx / N; p = p1 + (size_t)idx * 3;
    } else if (idx < tot0 + B * M) {
        int j = idx - tot0;
        cl = 1; b = j / M; p = p2 + (size_t)j * 3;
    } else return;
    int bin = binOf(p[0]);
    int rank = atomicAdd(&g_cnt[cl][b][bin], 1);
    g_aux[idx] = (bin << 16) | rank;
}

__global__ __launch_bounds__(NB) void k_scan(int B, int N, int M) {
    int cl = blockIdx.x / B, b = blockIdx.x % B;
    int n = cl ? M : N;
    __shared__ int sh[NB];
    int t = threadIdx.x;
    int c = g_cnt[cl][b][t];
    sh[t] = c;
    __syncthreads();
    for (int off = 1; off < NB; off <<= 1) {
        int v = (t >= off) ? sh[t - off] : 0;
        __syncthreads();
        sh[t] += v;
        __syncthreads();
    }
    g_start[cl][b][t] = sh[t] - c;
    if (t == NB - 1) {
        g_start[cl][b][NB] = n;
        // +inf pad entry at index n: can never win a min.
        g_pt[cl][b][n] = make_float4(0.f, 0.f, 0.f, __int_as_float(0x7F800000));
    }
}

// Atomic-free scatter: one STG.128 per point.
__global__ void k_scatter(const float* __restrict__ p1, const float* __restrict__ p2,
                          int B, int N, int M)
{
    int idx = blockIdx.x * blockDim.x + threadIdx.x;
    int tot0 = B * N;
    int cl, b; const float* p;
    if (idx < tot0) {
        cl = 0; b = idx / N; p = p1 + (size_t)idx * 3;
    } else if (idx < tot0 + B * M) {
        int j = idx - tot0;
        cl = 1; b = j / M; p = p2 + (size_t)j * 3;
    } else return;
    float x = p[0], y = p[1], z = p[2];
    int aux = g_aux[idx];
    int bin = aux >> 16, rank = aux & 0xFFFF;
    int pos = __ldg(&g_start[cl][b][bin]) + rank;
    g_pt[cl][b][pos] = make_float4(x, y, z, 0.5f * (x * x + y * y + z * z));
}

// Largest bin with st[bin] <= target.
__device__ __forceinline__ int binFromRank(const int* __restrict__ st, int target) {
    int lo = 0, hi = NB;
#pragma unroll
    for (int it = 0; it < 9; it++) {
        int mid = (lo + hi) >> 1;
        if (__ldg(&st[mid]) <= target) lo = mid; else hi = mid;
    }
    return lo;
}

// Pass 1: QPT=2 queries/thread over one shared smem window; per-lane exact
// finish test; unfinished queries enqueue an exact self-window for pass 2.
__global__ __launch_bounds__(TPB) void k_query(int B, int N, int M,
                                               float invBN, float invBM,
                                               float* __restrict__ out)
{
    __shared__ float4 sPairs[2 * SMXP];   // 32 KB staged ref pair window

    const int dir = blockIdx.z;           // 0: p1->p2, 1: p2->p1
    const int b   = blockIdx.y;
    const int nq  = dir ? M : N;
    const int nr  = dir ? N : M;
    const int q0  = blockIdx.x * QBLK;
    const float INFv = __int_as_float(0x7F800000);
    const float invW = dir ? invBM : invBN;

    const int qc = dir, rc = 1 - dir;

    int   qidx[QPT];
    float qx[QPT], qy[QPT], qz[QPT], q2[QPT];
#pragma unroll
    for (int j = 0; j < QPT; j++) {
        int qi = q0 + j * TPB + threadIdx.x;
        qidx[j] = qi;
        int qic = min(qi, nq - 1);
        float4 qv = __ldg(&g_pt[qc][b][qic]);
        qx[j] = qv.x; qy[j] = qv.y; qz[j] = qv.z;
        q2[j] = 2.0f * qv.w;
    }

    // Block query x-range (queries are x-sorted).
    const int qe = min(q0 + QBLK, nq) - 1;
    float qxmin = __ldg(&g_pt[qc][b][q0]).x;
    float qxmax = __ldg(&g_pt[qc][b][qe]).x;

    const int* __restrict__ st = g_start[rc][b];

    int rank0 = __ldg(&st[binOf(qxmin)]);
    int rank1 = __ldg(&st[min(binOf(qxmax) + 1, NB)]);
    int bL = (rank0 > WIN) ? binFromRank(st, rank0 - WIN) : 0;
    int bR = (rank1 + WIN < nr) ? binFromRank(st, rank1 + WIN) : NB - 1;

    int pLo = __ldg(&st[bL]) >> 1;
    int pHi = (__ldg(&st[bR + 1]) + 1) >> 1;
    const int bQL = binOf(qxmin), bQR = binOf(qxmax);
    while (pHi - pLo > SMXP) {   // rare smem clamp; shrink away from home bins
        if (bR > bQR)      { bR--; pHi = (__ldg(&st[bR + 1]) + 1) >> 1; }
        else if (bL < bQL) { bL++; pLo = __ldg(&st[bL]) >> 1; }
        else break;
    }
    int nPairs = min(pHi - pLo, SMXP);

    {   // cooperative stage + transpose to pair-packed layout
        const float4* __restrict__ src = &g_pt[rc][b][0];
        for (int i = threadIdx.x; i < nPairs; i += TPB) {
            int p = pLo + i;
            float4 P0 = __ldg(&src[2 * p]);
            float4 P1 = __ldg(&src[2 * p + 1]);   // may hit the pad entry
            sPairs[2 * i]     = make_float4(P0.x, P1.x, P0.y, P1.y);
            sPairs[2 * i + 1] = make_float4(P0.z, P1.z, P0.w, P1.w);
        }
    }
    __syncthreads();

    unsigned long long nqx[QPT], nqy[QPT], nqz[QPT];
    float mnA[QPT], mnB[QPT];
#pragma unroll
    for (int j = 0; j < QPT; j++) {
        nqx[j] = pk2(-qx[j], -qx[j]);
        nqy[j] = pk2(-qy[j], -qy[j]);
        nqz[j] = pk2(-qz[j], -qz[j]);
        mnA[j] = INFv; mnB[j] = INFv;
    }

    {   // packed-FFMA2 smem scan, QPT queries per staged pair
        const ulonglong2* __restrict__ sp = (const ulonglong2*)sPairs;
#pragma unroll 4
        for (int p = 0; p < nPairs; p++) {
            ulonglong2 av = sp[2 * p];
            ulonglong2 cv = sp[2 * p + 1];
#pragma unroll
            for (int j = 0; j < QPT; j++) {
                unsigned long long s = fma2(av.x, nqx[j],
                                       fma2(av.y, nqy[j],
                                       fma2(cv.x, nqz[j], cv.y)));
                float lo, hi;
                unpk2(s, lo, hi);
                mnA[j] = fminf(mnA[j], lo);
                mnB[j] = fminf(mnB[j], hi);
            }
        }
    }

    // Per-query exact finish test, contribution, overflow enqueue.
    const int lane = threadIdx.x & 31;
    float contrib = 0.0f;
    bool  need[QPT];
    float dnn[QPT];
#pragma unroll
    for (int j = 0; j < QPT; j++) {
        float best = fmaf(2.0f, fminf(mnA[j], mnB[j]), q2[j]);
        dnn[j] = fmaxf(best, 0.0f);
        bool doneL = (bL == 0);
        if (!doneL) { float dl = qx[j] - (GLO + bL * BW);       doneL = (dl * dl >= best); }
        bool doneR = (bR == NB - 1);
        if (!doneR) { float dr = (GLO + (bR + 1) * BW) - qx[j]; doneR = (dr * dr >= best); }
        bool valid = (qidx[j] < nq);
        need[j] = valid && !(doneL && doneR);
        if (valid && !need[j]) contrib += dnn[j] * invW;
    }
#pragma unroll
    for (int o = 16; o > 0; o >>= 1)
        contrib += __shfl_xor_sync(FULLM, contrib, o);
    if (lane == 0 && contrib != 0.0f) atomicAdd(out, contrib);

#pragma unroll
    for (int j = 0; j < QPT; j++) {
        unsigned m = __ballot_sync(FULLM, need[j]);
        if (m) {
            int leader = __ffs(m) - 1;
            int baseIdx = 0;
            if (lane == leader) baseIdx = atomicAdd(&g_ovfCnt, __popc(m));
            baseIdx = __shfl_sync(FULLM, baseIdx, leader);
            if (need[j]) {
                float r = sqrtf(dnn[j]);   // bound point lies inside window
                int binLo = binOf(qx[j] - r);
                int binHi = binOf(qx[j] + r);
                int s0 = __ldg(&st[binLo]);
                int s1 = __ldg(&st[binHi + 1]);
                int off = __popc(m & ((1u << lane) - 1));
                int code = qidx[j] | (b << 14) | (dir << 16);
                g_ovf[baseIdx + off] = make_int4(code, s0, s1, 0);
            }
        }
    }
}

// Pass 2: one warp per overflow query; lanes stride the point range.
// 4x unrolled with independent accumulators for MLP.
__global__ __launch_bounds__(256) void k_ovf(int B, int N, int M,
                                             float invBN, float invBM,
                                             float* __restrict__ out)
{
    const int nOvf = g_ovfCnt;
    const int lane = threadIdx.x & 31;
    int w  = (blockIdx.x * blockDim.x + threadIdx.x) >> 5;
    const int nW = (gridDim.x * blockDim.x) >> 5;
    const float INFv = __int_as_float(0x7F800000);

    for (int e = w; e < nOvf; e += nW) {
        int4 ent = g_ovf[e];
        const int code = ent.x;
        const int qic = code & 0x3FFF;
        const int b   = (code >> 14) & 3;
        const int dir = (code >> 16) & 1;
        const int qc = dir, rc = 1 - dir;

        float4 qv = __ldg(&g_pt[qc][b][qic]);
        const float qx = qv.x, qy = qv.y, qz = qv.z;
        const float q2 = 2.0f * qv.w;

        const float4* __restrict__ base = &g_pt[rc][b][0];
        float m0 = INFv, m1 = INFv, m2 = INFv, m3 = INFv;
        int p = ent.y + lane;
        for (; p + 96 < ent.z; p += 128) {
            float4 r0 = __ldg(&base[p]);
            float4 r1 = __ldg(&base[p + 32]);
            float4 r2 = __ldg(&base[p + 64]);
            float4 r3 = __ldg(&base[p + 96]);
            m0 = fminf(m0, fmaf(r0.x, -qx, fmaf(r0.y, -qy, fmaf(r0.z, -qz, r0.w))));
            m1 = fminf(m1, fmaf(r1.x, -qx, fmaf(r1.y, -qy, fmaf(r1.z, -qz, r1.w))));
            m2 = fminf(m2, fmaf(r2.x, -qx, fmaf(r2.y, -qy, fmaf(r2.z, -qz, r2.w))));
            m3 = fminf(m3, fmaf(r3.x, -qx, fmaf(r3.y, -qy, fmaf(r3.z, -qz, r3.w))));
        }
        for (; p < ent.z; p += 32) {
            float4 r0 = __ldg(&base[p]);
            m0 = fminf(m0, fmaf(r0.x, -qx, fmaf(r0.y, -qy, fmaf(r0.z, -qz, r0.w))));
        }
        float mn = fminf(fminf(m0, m1), fminf(m2, m3));
#pragma unroll
        for (int o = 16; o > 0; o >>= 1)
            mn = fminf(mn, __shfl_xor_sync(FULLM, mn, o));
        if (lane == 0) {
            float dnn = fmaxf(fmaf(2.0f, mn, q2), 0.0f);
            atomicAdd(out, dnn * (dir ? invBM : invBN));
        }
    }
}

extern "C" void kernel_launch(void* const* d_in, const int* in_sizes, int n_in,
                              void* d_out, int out_size)
{
    const float* p1 = (const float*)d_in[0];
    const float* p2 = (const float*)d_in[1];

    const int B = 4;
    const int N = in_sizes[0] / (B * 3);
    const int M = in_sizes[1] / (B * 3);

    k_zero<<<(2 * MAXB * NB + 255) / 256, 256>>>((float*)d_out);

    const int totPts = B * (N + M);
    k_hist<<<(totPts + 255) / 256, 256>>>(p1, p2, B, N, M);

    k_scan<<<2 * B, NB>>>(B, N, M);

    k_scatter<<<(totPts + 255) / 256, 256>>>(p1, p2, B, N, M);

    const int maxNM = N > M ? N : M;
    dim3 qgrid((maxNM + QBLK - 1) / QBLK, B, 2);
    k_query<<<qgrid, TPB>>>(B, N, M,
                            1.0f / (float)(B * N), 1.0f / (float)(B * M),
                            (float*)d_out);

    k_ovf<<<296, 256>>>(B, N, M,
                        1.0f / (float)(B * N), 1.0f / (float)(B * M),
                        (float*)d_out);
}

// round 16
// speedup vs baseline: 1.0711x; 1.0711x over previous
#include <cuda_runtime.h>
#include <cuda_bf16.h>

#define NB     512
#define GLO    (-6.0f)
#define BW     (12.0f / NB)
#define INVW   (NB / 12.0f)
#define MAXB   4
#define MAXPTS 8192
#define MAXPR  (MAXPTS / 2)
#define FULLM  0xFFFFFFFFu
#define WIN    512      // rank half-width around block's home ranks
#define TPB    128
#define QPT    2
#define QBLK   (TPB * QPT)   // 256 queries per block
#define SMXP   1024     // max staged pairs (32 KB smem)
#define MAXQ   (2 * MAXB * MAXPTS)

// Pair p of (cl,b): g_pk[cl][b][2p] = {x0,x1,y0,y1},
// g_pk[cl][b][2p+1] = {z0,z1,w0,w1}, w = 0.5*||p||^2. x-bin sorted.
__device__ int    g_cnt[2][MAXB][NB];       // histogram counts
__device__ int    g_start[2][MAXB][NB + 1];
__device__ float4 g_pk[2][MAXB][2 * MAXPR];
__device__ int    g_aux[MAXQ];              // per input point: bin<<16 | rank
__device__ int    g_ovfCnt;
__device__ int4   g_ovf[MAXQ];              // {code, s0, s1, pad}

__device__ __forceinline__ int binOf(float x) {
    int c = (int)floorf((x - GLO) * INVW);
    return min(max(c, 0), NB - 1);
}

// ---- packed f32x2 helpers ----
__device__ __forceinline__ unsigned long long pk2(float lo, float hi) {
    unsigned long long v;
    asm("mov.b64 %0, {%1, %2};" : "=l"(v) : "f"(lo), "f"(hi));
    return v;
}
__device__ __forceinline__ unsigned long long fma2(unsigned long long a,
                                                   unsigned long long b,
                                                   unsigned long long c) {
    unsigned long long d;
    asm("fma.rn.f32x2 %0, %1, %2, %3;" : "=l"(d) : "l"(a), "l"(b), "l"(c));
    return d;
}
__device__ __forceinline__ void unpk2(unsigned long long v, float& lo, float& hi) {
    asm("mov.b64 {%0, %1}, %2;" : "=f"(lo), "=f"(hi) : "l"(v));
}

// ---------------- setup ----------------

__global__ void k_zero(float* out) {
    int i = blockIdx.x * blockDim.x + threadIdx.x;
    int* c = &g_cnt[0][0][0];
    if (i < 2 * MAXB * NB) c[i] = 0;
    if (i == 0) { out[0] = 0.0f; g_ovfCnt = 0; }
}

// Histogram; also records each point's (bin, in-bin rank) for atomic-free scatter.
__global__ void k_hist(const float* __restrict__ p1, const float* __restrict__ p2,
                       int B, int N, int M)
{
    int idx = blockIdx.x * blockDim.x + threadIdx.x;
    int tot0 = B * N;
    int cl, b; const float* p;
    if (idx < tot0) {
        cl = 0; b = idx / N; p = p1 + (size_t)idx * 3;
    } else if (idx < tot0 + B * M) {
        int j = idx - tot0;
        cl = 1; b = j / M; p = p2 + (size_t)j * 3;
    } else return;
    int bin = binOf(p[0]);
    int rank = atomicAdd(&g_cnt[cl][b][bin], 1);
    g_aux[idx] = (bin << 16) | rank;
}

__global__ __launch_bounds__(NB) void k_scan(int B, int N, int M) {
    int cl = blockIdx.x / B, b = blockIdx.x % B;
    int n = cl ? M : N;
    __shared__ int sh[NB];
    int t = threadIdx.x;
    int c = g_cnt[cl][b][t];
    sh[t] = c;
    __syncthreads();
    for (int off = 1; off < NB; off <<= 1) {
        int v = (t >= off) ? sh[t - off] : 0;
        __syncthreads();
        sh[t] += v;
        __syncthreads();
    }
    g_start[cl][b][t] = sh[t] - c;
    if (t == NB - 1) {
        g_start[cl][b][NB] = n;
        if (n & 1)   // pad the unwritten odd half so it can never win a min
            g_pk[cl][b][2 * (n >> 1) + 1].w = __int_as_float(0x7F800000);
    }
}

// Atomic-free scatter using saved (bin, rank).
__global__ void k_scatter(const float* __restrict__ p1, const float* __restrict__ p2,
                          int B, int N, int M)
{
    int idx = blockIdx.x * blockDim.x + threadIdx.x;
    int tot0 = B * N;
    int cl, b; const float* p;
    if (idx < tot0) {
        cl = 0; b = idx / N; p = p1 + (size_t)idx * 3;
    } else if (idx < tot0 + B * M) {
        int j = idx - tot0;
        cl = 1; b = j / M; p = p2 + (size_t)j * 3;
    } else return;
    float x = p[0], y = p[1], z = p[2];
    int aux = g_aux[idx];
    int bin = aux >> 16, rank = aux & 0xFFFF;
    int pos = __ldg(&g_start[cl][b][bin]) + rank;
    int pr = pos >> 1, hh = pos & 1;
    float* Ap = (float*)&g_pk[cl][b][2 * pr];
    float* Bp = (float*)&g_pk[cl][b][2 * pr + 1];
    Ap[hh] = x;  Ap[2 + hh] = y;
    Bp[hh] = z;  Bp[2 + hh] = 0.5f * (x * x + y * y + z * z);
}

// Largest bin with st[bin] <= target.
__device__ __forceinline__ int binFromRank(const int* __restrict__ st, int target) {
    int lo = 0, hi = NB;
#pragma unroll
    for (int it = 0; it < 9; it++) {
        int mid = (lo + hi) >> 1;
        if (__ldg(&st[mid]) <= target) lo = mid; else hi = mid;
    }
    return lo;
}

// Pass 1: QPT=2 queries/thread over one shared smem window; per-lane exact
// finish test; unfinished queries enqueue an exact self-window for pass 2.
__global__ __launch_bounds__(TPB) void k_query(int B, int N, int M,
                                               float invBN, float invBM,
                                               float* __restrict__ out)
{
    __shared__ float4 sPairs[2 * SMXP];   // 32 KB staged ref pair window

    const int dir = blockIdx.z;           // 0: p1->p2, 1: p2->p1
    const int b   = blockIdx.y;
    const int nq  = dir ? M : N;
    const int nr  = dir ? N : M;
    const int q0  = blockIdx.x * QBLK;
    const float INFv = __int_as_float(0x7F800000);
    const float invW = dir ? invBM : invBN;

    const int qc = dir, rc = 1 - dir;

    int   qidx[QPT];
    float qx[QPT], qy[QPT], qz[QPT], q2[QPT];
#pragma unroll
    for (int j = 0; j < QPT; j++) {
        int qi = q0 + j * TPB + threadIdx.x;
        qidx[j] = qi;
        int qic = min(qi, nq - 1);
        float4 qa = g_pk[qc][b][2 * (qic >> 1)];
        float4 qb = g_pk[qc][b][2 * (qic >> 1) + 1];
        int h = qic & 1;
        qx[j] = h ? qa.y : qa.x;
        qy[j] = h ? qa.w : qa.z;
        qz[j] = h ? qb.y : qb.x;
        q2[j] = 2.0f * (h ? qb.w : qb.z);
    }

    // Block query x-range (queries are x-sorted).
    const int qe = min(q0 + QBLK, nq) - 1;
    float4 fa = g_pk[qc][b][2 * (q0 >> 1)];
    float qxmin = (q0 & 1) ? fa.y : fa.x;
    float4 la = g_pk[qc][b][2 * (qe >> 1)];
    float qxmax = (qe & 1) ? la.y : la.x;

    const int* __restrict__ st = g_start[rc][b];

    int rank0 = __ldg(&st[binOf(qxmin)]);
    int rank1 = __ldg(&st[min(binOf(qxmax) + 1, NB)]);
    int bL = (rank0 > WIN) ? binFromRank(st, rank0 - WIN) : 0;
    int bR = (rank1 + WIN < nr) ? binFromRank(st, rank1 + WIN) : NB - 1;

    int pLo = __ldg(&st[bL]) >> 1;
    int pHi = (__ldg(&st[bR + 1]) + 1) >> 1;
    const int bQL = binOf(qxmin), bQR = binOf(qxmax);
    while (pHi - pLo > SMXP) {   // rare smem clamp; shrink away from home bins
        if (bR > bQR)      { bR--; pHi = (__ldg(&st[bR + 1]) + 1) >> 1; }
        else if (bL < bQL) { bL++; pLo = __ldg(&st[bL]) >> 1; }
        else break;
    }
    int nPairs = min(pHi - pLo, SMXP);

    {   // cooperative stage (straight copy)
        const float4* __restrict__ src = &g_pk[rc][b][2 * pLo];
        for (int i = threadIdx.x; i < 2 * nPairs; i += TPB)
            sPairs[i] = __ldg(&src[i]);
    }
    __syncthreads();

    unsigned long long nqx[QPT], nqy[QPT], nqz[QPT];
    float mnA[QPT], mnB[QPT];
#pragma unroll
    for (int j = 0; j < QPT; j++) {
        nqx[j] = pk2(-qx[j], -qx[j]);
        nqy[j] = pk2(-qy[j], -qy[j]);
        nqz[j] = pk2(-qz[j], -qz[j]);
        mnA[j] = INFv; mnB[j] = INFv;
    }

    {   // packed-FFMA2 smem scan, QPT queries per staged pair
        const ulonglong2* __restrict__ sp = (const ulonglong2*)sPairs;
#pragma unroll 4
        for (int p = 0; p < nPairs; p++) {
            ulonglong2 av = sp[2 * p];
            ulonglong2 cv = sp[2 * p + 1];
#pragma unroll
            for (int j = 0; j < QPT; j++) {
                unsigned long long s = fma2(av.x, nqx[j],
                                       fma2(av.y, nqy[j],
                                       fma2(cv.x, nqz[j], cv.y)));
                float lo, hi;
                unpk2(s, lo, hi);
                mnA[j] = fminf(mnA[j], lo);
                mnB[j] = fminf(mnB[j], hi);
            }
        }
    }

    // Per-query exact finish test, contribution, overflow enqueue.
    const int lane = threadIdx.x & 31;
    float contrib = 0.0f;
    bool  need[QPT];
    float dnn[QPT];
#pragma unroll
    for (int j = 0; j < QPT; j++) {
        float best = fmaf(2.0f, fminf(mnA[j], mnB[j]), q2[j]);
        dnn[j] = fmaxf(best, 0.0f);
        bool doneL = (bL == 0);
        if (!doneL) { float dl = qx[j] - (GLO + bL * BW);       doneL = (dl * dl >= best); }
        bool doneR = (bR == NB - 1);
        if (!doneR) { float dr = (GLO + (bR + 1) * BW) - qx[j]; doneR = (dr * dr >= best); }
        bool valid = (qidx[j] < nq);
        need[j] = valid && !(doneL && doneR);
        if (valid && !need[j]) contrib += dnn[j] * invW;
    }
#pragma unroll
    for (int o = 16; o > 0; o >>= 1)
        contrib += __shfl_xor_sync(FULLM, contrib, o);
    if (lane == 0 && contrib != 0.0f) atomicAdd(out, contrib);

#pragma unroll
    for (int j = 0; j < QPT; j++) {
        unsigned m = __ballot_sync(FULLM, need[j]);
        if (m) {
            int leader = __ffs(m) - 1;
            int baseIdx = 0;
            if (lane == leader) baseIdx = atomicAdd(&g_ovfCnt, __popc(m));
            baseIdx = __shfl_sync(FULLM, baseIdx, leader);
            if (need[j]) {
                float r = sqrtf(dnn[j]);   // bound point lies inside window
                int binLo = binOf(qx[j] - r);
                int binHi = binOf(qx[j] + r);
                int s0 = __ldg(&st[binLo]);
                int s1 = __ldg(&st[binHi + 1]);
                int off = __popc(m & ((1u << lane) - 1));
                int code = qidx[j] | (b << 14) | (dir << 16);
                g_ovf[baseIdx + off] = make_int4(code, s0, s1, 0);
            }
        }
    }
}

// Pass 2: one warp per overflow query; lanes stride the pair range.
// 4x unrolled with independent accumulators for MLP.
__global__ __launch_bounds__(256) void k_ovf(int B, int N, int M,
                                             float invBN, float invBM,
                                             float* __restrict__ out)
{
    const int nOvf = g_ovfCnt;
    const int lane = threadIdx.x & 31;
    int w  = (blockIdx.x * blockDim.x + threadIdx.x) >> 5;
    const int nW = (gridDim.x * blockDim.x) >> 5;
    const float INFv = __int_as_float(0x7F800000);

    for (int e = w; e < nOvf; e += nW) {
        int4 ent = g_ovf[e];
        const int code = ent.x;
        const int qic = code & 0x3FFF;
        const int b   = (code >> 14) & 3;
        const int dir = (code >> 16) & 1;
        const int qc = dir, rc = 1 - dir;

        float4 qa = g_pk[qc][b][2 * (qic >> 1)];
        float4 qb = g_pk[qc][b][2 * (qic >> 1) + 1];
        const int h = qic & 1;
        const float qx = h ? qa.y : qa.x;
        const float qy = h ? qa.w : qa.z;
        const float qz = h ? qb.y : qb.x;
        const float q2 = 2.0f * (h ? qb.w : qb.z);

        const unsigned long long nqx = pk2(-qx, -qx);
        const unsigned long long nqy = pk2(-qy, -qy);
        const unsigned long long nqz = pk2(-qz, -qz);

        unsigned long long mA0 = pk2(INFv, INFv), mA1 = mA0, mA2 = mA0, mA3 = mA0;

        const ulonglong2* __restrict__ base = (const ulonglong2*)&g_pk[rc][b][0];
        int p0 = ent.y >> 1, p1 = (ent.z + 1) >> 1;
        int p = p0 + lane;

        // 4x unrolled: 8 independent LDG.128 in flight per lane.
        for (; p + 96 < p1; p += 128) {
            ulonglong2 a0 = __ldg(base + 2 * p);
            ulonglong2 c0 = __ldg(base + 2 * p + 1);
            ulonglong2 a1 = __ldg(base + 2 * (p + 32));
            ulonglong2 c1 = __ldg(base + 2 * (p + 32) + 1);
            ulonglong2 a2 = __ldg(base + 2 * (p + 64));
            ulonglong2 c2 = __ldg(base + 2 * (p + 64) + 1);
            ulonglong2 a3 = __ldg(base + 2 * (p + 96));
            ulonglong2 c3 = __ldg(base + 2 * (p + 96) + 1);
            unsigned long long s0 = fma2(a0.x, nqx, fma2(a0.y, nqy, fma2(c0.x, nqz, c0.y)));
            unsigned long long s1 = fma2(a1.x, nqx, fma2(a1.y, nqy, fma2(c1.x, nqz, c1.y)));
            unsigned long long s2 = fma2(a2.x, nqx, fma2(a2.y, nqy, fma2(c2.x, nqz, c2.y)));
            unsigned long long s3 = fma2(a3.x, nqx, fma2(a3.y, nqy, fma2(c3.x, nqz, c3.y)));
            float l0, h0, l1, h1, l2, h2, l3, h3, ml0, mh0, ml1, mh1, ml2, mh2, ml3, mh3;
            unpk2(s0, l0, h0); unpk2(mA0, ml0, mh0);
            mA0 = pk2(fminf(ml0, l0), fminf(mh0, h0));
            unpk2(s1, l1, h1); unpk2(mA1, ml1, mh1);
            mA1 = pk2(fminf(ml1, l1), fminf(mh1, h1));
            unpk2(s2, l2, h2); unpk2(mA2, ml2, mh2);
            mA2 = pk2(fminf(ml2, l2), fminf(mh2, h2));
            unpk2(s3, l3, h3); unpk2(mA3, ml3, mh3);
            mA3 = pk2(fminf(ml3, l3), fminf(mh3, h3));
        }
        for (; p < p1; p += 32) {
            ulonglong2 a0 = __ldg(base + 2 * p);
            ulonglong2 c0 = __ldg(base + 2 * p + 1);
            unsigned long long s0 = fma2(a0.x, nqx, fma2(a0.y, nqy, fma2(c0.x, nqz, c0.y)));
            float l0, h0, ml0, mh0;
            unpk2(s0, l0, h0); unpk2(mA0, ml0, mh0);
            mA0 = pk2(fminf(ml0, l0), fminf(mh0, h0));
        }
        float l0, h0, l1, h1, l2, h2, l3, h3;
        unpk2(mA0, l0, h0); unpk2(mA1, l1, h1);
        unpk2(mA2, l2, h2); unpk2(mA3, l3, h3);
        float mn = fminf(fminf(fminf(l0, h0), fminf(l1, h1)),
                         fminf(fminf(l2, h2), fminf(l3, h3)));
#pragma unroll
        for (int o = 16; o > 0; o >>= 1)
            mn = fminf(mn, __shfl_xor_sync(FULLM, mn, o));
        if (lane == 0) {
            float dnn = fmaxf(fmaf(2.0f, mn, q2), 0.0f);
            atomicAdd(out, dnn * (dir ? invBM : invBN));
        }
    }
}

extern "C" void kernel_launch(void* const* d_in, const int* in_sizes, int n_in,
                              void* d_out, int out_size)
{
    const float* p1 = (const float*)d_in[0];
    const float* p2 = (const float*)d_in[1];

    const int B = 4;
    const int N = in_sizes[0] / (B * 3);
    const int M = in_sizes[1] / (B * 3);

    k_zero<<<(2 * MAXB * NB + 255) / 256, 256>>>((float*)d_out);

    const int totPts = B * (N + M);
    k_hist<<<(totPts + 255) / 256, 256>>>(p1, p2, B, N, M);

    k_scan<<<2 * B, NB>>>(B, N, M);

    k_scatter<<<(totPts + 255) / 256, 256>>>(p1, p2, B, N, M);

    const int maxNM = N > M ? N : M;
    dim3 qgrid((maxNM + QBLK - 1) / QBLK, B, 2);
    k_query<<<qgrid, TPB>>>(B, N, M,
                            1.0f / (float)(B * N), 1.0f / (float)(B * M),
                            (float*)d_out);

    k_ovf<<<296, 256>>>(B, N, M,
                        1.0f / (float)(B * N), 1.0f / (float)(B * M),
                        (float*)d_out);
}

// round 17
// speedup vs baseline: 1.1546x; 1.0780x over previous
#include <cuda_runtime.h>
#include <cuda_bf16.h>

#define NB     512
#define GLO    (-6.0f)
#define BW     (12.0f / NB)
#define INVW   (NB / 12.0f)
#define MAXB   4
#define MAXPTS 8192
#define MAXPR  (MAXPTS / 2)
#define FULLM  0xFFFFFFFFu
#define WIN    512      // rank half-width around block's home ranks
#define TPB    128
#define QPT    2
#define QBLK   (TPB * QPT)   // 256 queries per block
#define SMXP   1024     // max staged pairs (32 KB smem)
#define MAXQ   (2 * MAXB * MAXPTS)

// Pair p of (cl,b): g_pk[cl][b][2p] = {x0,x1,y0,y1},
// g_pk[cl][b][2p+1] = {z0,z1,w0,w1}, w = 0.5*||p||^2. x-bin sorted.
// g_cnt starts zero (static init) and is re-zeroed by k_scan every run.
__device__ int    g_cnt[2][MAXB][NB];       // histogram counts (self-cleaning)
__device__ int    g_start[2][MAXB][NB + 1];
__device__ float4 g_pk[2][MAXB][2 * MAXPR];
__device__ int    g_aux[MAXQ];              // per input point: bin<<16 | rank
__device__ int    g_ovfCnt;
__device__ int4   g_ovf[MAXQ];              // {code, s0, s1, pad}

__device__ __forceinline__ int binOf(float x) {
    int c = (int)floorf((x - GLO) * INVW);
    return min(max(c, 0), NB - 1);
}

// ---- packed f32x2 helpers ----
__device__ __forceinline__ unsigned long long pk2(float lo, float hi) {
    unsigned long long v;
    asm("mov.b64 %0, {%1, %2};" : "=l"(v) : "f"(lo), "f"(hi));
    return v;
}
__device__ __forceinline__ unsigned long long fma2(unsigned long long a,
                                                   unsigned long long b,
                                                   unsigned long long c) {
    unsigned long long d;
    asm("fma.rn.f32x2 %0, %1, %2, %3;" : "=l"(d) : "l"(a), "l"(b), "l"(c));
    return d;
}
__device__ __forceinline__ void unpk2(unsigned long long v, float& lo, float& hi) {
    asm("mov.b64 {%0, %1}, %2;" : "=f"(lo), "=f"(hi) : "l"(v));
}

// ---------------- setup ----------------

// Histogram; also records each point's (bin, in-bin rank) for atomic-free scatter.
// Relies on g_cnt being zero: static zero-init on first run, re-zeroed by
// k_scan (which executes after k_hist in every replay) for subsequent runs.
__global__ void k_hist(const float* __restrict__ p1, const float* __restrict__ p2,
                       int B, int N, int M)
{
    int idx = blockIdx.x * blockDim.x + threadIdx.x;
    int tot0 = B * N;
    int cl, b; const float* p;
    if (idx < tot0) {
        cl = 0; b = idx / N; p = p1 + (size_t)idx * 3;
    } else if (idx < tot0 + B * M) {
        int j = idx - tot0;
        cl = 1; b = j / M; p = p2 + (size_t)j * 3;
    } else return;
    int bin = binOf(p[0]);
    int rank = atomicAdd(&g_cnt[cl][b][bin], 1);
    g_aux[idx] = (bin << 16) | rank;
}

// Scan counts -> bin starts; re-zero g_cnt for the next replay; zero the
// accumulator and overflow counter consumed later in THIS replay.
__global__ __launch_bounds__(NB) void k_scan(int B, int N, int M,
                                             float* __restrict__ out)
{
    int cl = blockIdx.x / B, b = blockIdx.x % B;
    int n = cl ? M : N;
    __shared__ int sh[NB];
    int t = threadIdx.x;
    int c = g_cnt[cl][b][t];
    g_cnt[cl][b][t] = 0;          // self-clean for next replay
    sh[t] = c;
    __syncthreads();
    for (int off = 1; off < NB; off <<= 1) {
        int v = (t >= off) ? sh[t - off] : 0;
        __syncthreads();
        sh[t] += v;
        __syncthreads();
    }
    g_start[cl][b][t] = sh[t] - c;
    if (t == NB - 1) {
        g_start[cl][b][NB] = n;
        if (n & 1)   // pad the unwritten odd half so it can never win a min
            g_pk[cl][b][2 * (n >> 1) + 1].w = __int_as_float(0x7F800000);
    }
    if (blockIdx.x == 0 && t == 0) {
        out[0] = 0.0f;
        g_ovfCnt = 0;
    }
}

// Atomic-free scatter using saved (bin, rank).
__global__ void k_scatter(const float* __restrict__ p1, const float* __restrict__ p2,
                          int B, int N, int M)
{
    int idx = blockIdx.x * blockDim.x + threadIdx.x;
    int tot0 = B * N;
    int cl, b; const float* p;
    if (idx < tot0) {
        cl = 0; b = idx / N; p = p1 + (size_t)idx * 3;
    } else if (idx < tot0 + B * M) {
        int j = idx - tot0;
        cl = 1; b = j / M; p = p2 + (size_t)j * 3;
    } else return;
    float x = p[0], y = p[1], z = p[2];
    int aux = g_aux[idx];
    int bin = aux >> 16, rank = aux & 0xFFFF;
    int pos = __ldg(&g_start[cl][b][bin]) + rank;
    int pr = pos >> 1, hh = pos & 1;
    float* Ap = (float*)&g_pk[cl][b][2 * pr];
    float* Bp = (float*)&g_pk[cl][b][2 * pr + 1];
    Ap[hh] = x;  Ap[2 + hh] = y;
    Bp[hh] = z;  Bp[2 + hh] = 0.5f * (x * x + y * y + z * z);
}

// Largest bin with st[bin] <= target.
__device__ __forceinline__ int binFromRank(const int* __restrict__ st, int target) {
    int lo = 0, hi = NB;
#pragma unroll
    for (int it = 0; it < 9; it++) {
        int mid = (lo + hi) >> 1;
        if (__ldg(&st[mid]) <= target) lo = mid; else hi = mid;
    }
    return lo;
}

// Pass 1: QPT=2 queries/thread over one shared smem window; per-lane exact
// finish test; unfinished queries enqueue an exact self-window for pass 2.
__global__ __launch_bounds__(TPB) void k_query(int B, int N, int M,
                                               float invBN, float invBM,
                                               float* __restrict__ out)
{
    __shared__ float4 sPairs[2 * SMXP];   // 32 KB staged ref pair window

    const int dir = blockIdx.z;           // 0: p1->p2, 1: p2->p1
    const int b   = blockIdx.y;
    const int nq  = dir ? M : N;
    const int nr  = dir ? N : M;
    const int q0  = blockIdx.x * QBLK;
    const float INFv = __int_as_float(0x7F800000);
    const float invW = dir ? invBM : invBN;

    const int qc = dir, rc = 1 - dir;

    int   qidx[QPT];
    float qx[QPT], qy[QPT], qz[QPT], q2[QPT];
#pragma unroll
    for (int j = 0; j < QPT; j++) {
        int qi = q0 + j * TPB + threadIdx.x;
        qidx[j] = qi;
        int qic = min(qi, nq - 1);
        float4 qa = g_pk[qc][b][2 * (qic >> 1)];
        float4 qb = g_pk[qc][b][2 * (qic >> 1) + 1];
        int h = qic & 1;
        qx[j] = h ? qa.y : qa.x;
        qy[j] = h ? qa.w : qa.z;
        qz[j] = h ? qb.y : qb.x;
        q2[j] = 2.0f * (h ? qb.w : qb.z);
    }

    // Block query x-range (queries are x-sorted).
    const int qe = min(q0 + QBLK, nq) - 1;
    float4 fa = g_pk[qc][b][2 * (q0 >> 1)];
    float qxmin = (q0 & 1) ? fa.y : fa.x;
    float4 la = g_pk[qc][b][2 * (qe >> 1)];
    float qxmax = (qe & 1) ? la.y : la.x;

    const int* __restrict__ st = g_start[rc][b];

    int rank0 = __ldg(&st[binOf(qxmin)]);
    int rank1 = __ldg(&st[min(binOf(qxmax) + 1, NB)]);
    int bL = (rank0 > WIN) ? binFromRank(st, rank0 - WIN) : 0;
    int bR = (rank1 + WIN < nr) ? binFromRank(st, rank1 + WIN) : NB - 1;

    int pLo = __ldg(&st[bL]) >> 1;
    int pHi = (__ldg(&st[bR + 1]) + 1) >> 1;
    const int bQL = binOf(qxmin), bQR = binOf(qxmax);
    while (pHi - pLo > SMXP) {   // rare smem clamp; shrink away from home bins
        if (bR > bQR)      { bR--; pHi = (__ldg(&st[bR + 1]) + 1) >> 1; }
        else if (bL < bQL) { bL++; pLo = __ldg(&st[bL]) >> 1; }
        else break;
    }
    int nPairs = min(pHi - pLo, SMXP);

    {   // cooperative stage (straight copy)
        const float4* __restrict__ src = &g_pk[rc][b][2 * pLo];
        for (int i = threadIdx.x; i < 2 * nPairs; i += TPB)
            sPairs[i] = __ldg(&src[i]);
    }
    __syncthreads();

    unsigned long long nqx[QPT], nqy[QPT], nqz[QPT];
    float mnA[QPT], mnB[QPT];
#pragma unroll
    for (int j = 0; j < QPT; j++) {
        nqx[j] = pk2(-qx[j], -qx[j]);
        nqy[j] = pk2(-qy[j], -qy[j]);
        nqz[j] = pk2(-qz[j], -qz[j]);
        mnA[j] = INFv; mnB[j] = INFv;
    }

    {   // packed-FFMA2 smem scan, QPT queries per staged pair
        const ulonglong2* __restrict__ sp = (const ulonglong2*)sPairs;
#pragma unroll 4
        for (int p = 0; p < nPairs; p++) {
            ulonglong2 av = sp[2 * p];
            ulonglong2 cv = sp[2 * p + 1];
#pragma unroll
            for (int j = 0; j < QPT; j++) {
                unsigned long long s = fma2(av.x, nqx[j],
                                       fma2(av.y, nqy[j],
                                       fma2(cv.x, nqz[j], cv.y)));
                float lo, hi;
                unpk2(s, lo, hi);
                mnA[j] = fminf(mnA[j], lo);
                mnB[j] = fminf(mnB[j], hi);
            }
        }
    }

    // Per-query exact finish test, contribution, overflow enqueue.
    const int lane = threadIdx.x & 31;
    float contrib = 0.0f;
    bool  need[QPT];
    float dnn[QPT];
#pragma unroll
    for (int j = 0; j < QPT; j++) {
        float best = fmaf(2.0f, fminf(mnA[j], mnB[j]), q2[j]);
        dnn[j] = fmaxf(best, 0.0f);
        bool doneL = (bL == 0);
        if (!doneL) { float dl = qx[j] - (GLO + bL * BW);       doneL = (dl * dl >= best); }
        bool doneR = (bR == NB - 1);
        if (!doneR) { float dr = (GLO + (bR + 1) * BW) - qx[j]; doneR = (dr * dr >= best); }
        bool valid = (qidx[j] < nq);
        need[j] = valid && !(doneL && doneR);
        if (valid && !need[j]) contrib += dnn[j] * invW;
    }
#pragma unroll
    for (int o = 16; o > 0; o >>= 1)
        contrib += __shfl_xor_sync(FULLM, contrib, o);
    if (lane == 0 && contrib != 0.0f) atomicAdd(out, contrib);

#pragma unroll
    for (int j = 0; j < QPT; j++) {
        unsigned m = __ballot_sync(FULLM, need[j]);
        if (m) {
            int leader = __ffs(m) - 1;
            int baseIdx = 0;
            if (lane == leader) baseIdx = atomicAdd(&g_ovfCnt, __popc(m));
            baseIdx = __shfl_sync(FULLM, baseIdx, leader);
            if (need[j]) {
                float r = sqrtf(dnn[j]);   // bound point lies inside window
                int binLo = binOf(qx[j] - r);
                int binHi = binOf(qx[j] + r);
                int s0 = __ldg(&st[binLo]);
                int s1 = __ldg(&st[binHi + 1]);
                int off = __popc(m & ((1u << lane) - 1));
                int code = qidx[j] | (b << 14) | (dir << 16);
                g_ovf[baseIdx + off] = make_int4(code, s0, s1, 0);
            }
        }
    }
}

// Pass 2: one warp per overflow query; lanes stride the pair range.
__global__ __launch_bounds__(256) void k_ovf(int B, int N, int M,
                                             float invBN, float invBM,
                                             float* __restrict__ out)
{
    const int nOvf = g_ovfCnt;
    const int lane = threadIdx.x & 31;
    int w  = (blockIdx.x * blockDim.x + threadIdx.x) >> 5;
    const int nW = (gridDim.x * blockDim.x) >> 5;
    const float INFv = __int_as_float(0x7F800000);

    for (int e = w; e < nOvf; e += nW) {
        int4 ent = g_ovf[e];
        const int code = ent.x;
        const int qic = code & 0x3FFF;
        const int b   = (code >> 14) & 3;
        const int dir = (code >> 16) & 1;
        const int qc = dir, rc = 1 - dir;

        float4 qa = g_pk[qc][b][2 * (qic >> 1)];
        float4 qb = g_pk[qc][b][2 * (qic >> 1) + 1];
        const int h = qic & 1;
        const float qx = h ? qa.y : qa.x;
        const float qy = h ? qa.w : qa.z;
        const float qz = h ? qb.y : qb.x;
        const float q2 = 2.0f * (h ? qb.w : qb.z);

        const unsigned long long nqx = pk2(-qx, -qx);
        const unsigned long long nqy = pk2(-qy, -qy);
        const unsigned long long nqz = pk2(-qz, -qz);
        float mnA = INFv, mnB = INFv;

        const ulonglong2* __restrict__ base = (const ulonglong2*)&g_pk[rc][b][0];
        int p0 = ent.y >> 1, p1 = (ent.z + 1) >> 1;
        for (int p = p0 + lane; p < p1; p += 32) {
            ulonglong2 av = __ldg(base + 2 * p);
            ulonglong2 cv = __ldg(base + 2 * p + 1);
            unsigned long long s = fma2(av.x, nqx,
                                   fma2(av.y, nqy,
                                   fma2(cv.x, nqz, cv.y)));
            float lo, hi;
            unpk2(s, lo, hi);
            mnA = fminf(mnA, lo);
            mnB = fminf(mnB, hi);
        }
        float mn = fminf(mnA, mnB);
#pragma unroll
        for (int o = 16; o > 0; o >>= 1)
            mn = fminf(mn, __shfl_xor_sync(FULLM, mn, o));
        if (lane == 0) {
            float dnn = fmaxf(fmaf(2.0f, mn, q2), 0.0f);
            atomicAdd(out, dnn * (dir ? invBM : invBN));
        }
    }
}

extern "C" void kernel_launch(void* const* d_in, const int* in_sizes, int n_in,
                              void* d_out, int out_size)
{
    const float* p1 = (const float*)d_in[0];
    const float* p2 = (const float*)d_in[1];

    const int B = 4;
    const int N = in_sizes[0] / (B * 3);
    const int M = in_sizes[1] / (B * 3);

    const int totPts = B * (N + M);
    k_hist<<<(totPts + 255) / 256, 256>>>(p1, p2, B, N, M);

    k_scan<<<2 * B, NB>>>(B, N, M, (float*)d_out);

    k_scatter<<<(totPts + 255) / 256, 256>>>(p1, p2, B, N, M);

    const int maxNM = N > M ? N : M;
    dim3 qgrid((maxNM + QBLK - 1) / QBLK, B, 2);
    k_query<<<qgrid, TPB>>>(B, N, M,
                            1.0f / (float)(B * N), 1.0f / (float)(B * M),
                            (float*)d_out);

    k_ovf<<<296, 256>>>(B, N, M,
                        1.0f / (float)(B * N), 1.0f / (float)(B * M),
                        (float*)d_out);
}